// round 2
// baseline (speedup 1.0000x reference)
#include <cuda_runtime.h>
#include <math.h>

// Problem dims
#define BB 64
#define TT 512
#define EE 300
#define UU 256
#define GG 768
#define CC 20

// ------------------------------------------------------------------
// Scratch (device globals; allocation inside kernel_launch is banned)
// ------------------------------------------------------------------
__device__ float g_e  [BB * TT * EE];       // embedded input  [B*T, 300]
__device__ float g_xwf[BB * TT * GG];       // xw forward      [B*T, 768]
__device__ float g_xwb[BB * TT * GG];       // xw backward     [B*T, 768]
__device__ float g_h1 [BB * TT * 2 * UU];   // layer-1 output  [B*T, 512]
__device__ float g_h2 [BB * 2 * UU];        // layer-2 final   [B, 512]

// ------------------------------------------------------------------
// 1) Embedding gather: e[row, :] = emb[x[row], :]   (300 floats = 75 float4)
// ------------------------------------------------------------------
__global__ void gather_kernel(const int* __restrict__ x,
                              const float* __restrict__ emb,
                              float* __restrict__ e) {
    int row = blockIdx.x;
    int tid = threadIdx.x;
    if (tid < 75) {
        const float4* src = reinterpret_cast<const float4*>(emb + (size_t)x[row] * EE);
        float4*       dst = reinterpret_cast<float4*>(e + (size_t)row * EE);
        dst[tid] = src[tid];
    }
}

// ------------------------------------------------------------------
// 2) SGEMM with bias: C[M,N] = A[M,K] @ Bm[K,N] + bias[N]
//    BM=128, BN=128, BK=8, 256 threads, 8x8 register tile.
//    M % 128 == 0, N % 128 == 0 required; K arbitrary (guarded).
// ------------------------------------------------------------------
#define GBM 128
#define GBN 128
#define GBK 8

__global__ __launch_bounds__(256)
void sgemm_bias(const float* __restrict__ A, const float* __restrict__ Bm,
                const float* __restrict__ bias, float* __restrict__ C,
                int M, int N, int K) {
    __shared__ float As[GBK][GBM];
    __shared__ float Bs[GBK][GBN];

    int tid = threadIdx.x;
    int bm = blockIdx.y * GBM;
    int bn = blockIdx.x * GBN;

    int tr = tid / 16;        // 0..15 -> rows tr*8..tr*8+7
    int tc = tid % 16;        // 0..15 -> cols tc*8..tc*8+7

    int aRow = tid / 2;       // 0..127
    int aCol = (tid % 2) * 4; // 0 or 4
    int bRow = tid / 32;      // 0..7
    int bCol = (tid % 32) * 4;// 0..124

    float acc[8][8];
#pragma unroll
    for (int i = 0; i < 8; i++)
#pragma unroll
        for (int j = 0; j < 8; j++) acc[i][j] = 0.f;

    for (int k0 = 0; k0 < K; k0 += GBK) {
        // --- load A tile (128 x 8) ---
        if (k0 + aCol + 3 < K) {
            float4 v = *reinterpret_cast<const float4*>(&A[(size_t)(bm + aRow) * K + k0 + aCol]);
            As[aCol + 0][aRow] = v.x;
            As[aCol + 1][aRow] = v.y;
            As[aCol + 2][aRow] = v.z;
            As[aCol + 3][aRow] = v.w;
        } else {
#pragma unroll
            for (int i = 0; i < 4; i++) {
                int kk = k0 + aCol + i;
                As[aCol + i][aRow] = (kk < K) ? A[(size_t)(bm + aRow) * K + kk] : 0.f;
            }
        }
        // --- load B tile (8 x 128) ---
        {
            int kk = k0 + bRow;
            if (kk < K) {
                float4 v = *reinterpret_cast<const float4*>(&Bm[(size_t)kk * N + bn + bCol]);
                Bs[bRow][bCol + 0] = v.x;
                Bs[bRow][bCol + 1] = v.y;
                Bs[bRow][bCol + 2] = v.z;
                Bs[bRow][bCol + 3] = v.w;
            } else {
                Bs[bRow][bCol + 0] = 0.f;
                Bs[bRow][bCol + 1] = 0.f;
                Bs[bRow][bCol + 2] = 0.f;
                Bs[bRow][bCol + 3] = 0.f;
            }
        }
        __syncthreads();

#pragma unroll
        for (int k = 0; k < GBK; k++) {
            float a[8], b[8];
#pragma unroll
            for (int i = 0; i < 8; i++) a[i] = As[k][tr * 8 + i];
#pragma unroll
            for (int j = 0; j < 8; j++) b[j] = Bs[k][tc * 8 + j];
#pragma unroll
            for (int i = 0; i < 8; i++)
#pragma unroll
                for (int j = 0; j < 8; j++) acc[i][j] += a[i] * b[j];
        }
        __syncthreads();
    }

#pragma unroll
    for (int i = 0; i < 8; i++) {
#pragma unroll
        for (int j = 0; j < 8; j++) {
            int col = bn + tc * 8 + j;
            C[(size_t)(bm + tr * 8 + i) * N + col] = acc[i][j] + bias[col];
        }
    }
}

// ------------------------------------------------------------------
// 3) GRU recurrence (Keras reset_after=True), both directions in one grid.
//    Grid: 64 CTAs = 32 fwd + 32 bwd, each CTA owns 2 batch rows, 256 thr.
//    Thread u owns hidden unit u for both its batch rows.
//    rk streamed from L2 each step (786 KB, shared across CTAs of a dir).
// ------------------------------------------------------------------
__device__ __forceinline__ float sigmoidf_(float v) {
    return 1.f / (1.f + expf(-v));
}

__global__ __launch_bounds__(256)
void gru_layer(const float* __restrict__ xw_f, const float* __restrict__ xw_b,
               const float* __restrict__ rk_f, const float* __restrict__ rk_b,
               const float* __restrict__ bin_f, const float* __restrict__ bin_b,
               float* __restrict__ out_seq,   // [B*T, 512] or nullptr
               float* __restrict__ out_final) // [B, 512]  or nullptr
{
    int cta  = blockIdx.x;     // 0..63
    int dir  = cta >> 5;       // 0 fwd, 1 bwd
    int pair = cta & 31;
    int b0   = pair * 2;

    const float* xw  = dir ? xw_b  : xw_f;
    const float* rk  = dir ? rk_b  : rk_f;
    const float* bin = dir ? bin_b : bin_f;

    int u = threadIdx.x;       // 0..255

    __shared__ float hs[2][UU];
    hs[0][u] = 0.f;
    hs[1][u] = 0.f;

    const float bz = bin[u];
    const float br = bin[UU + u];
    const float bh = bin[2 * UU + u];

    const float* rku = rk + u;   // column base for this thread

    __syncthreads();

    for (int s = 0; s < TT; s++) {
        int t = dir ? (TT - 1 - s) : s;

        float az0 = bz, ar0 = br, ah0 = bh;
        float az1 = bz, ar1 = br, ah1 = bh;

#pragma unroll 4
        for (int k = 0; k < UU; k++) {
            float wz = __ldg(&rku[k * GG]);
            float wr = __ldg(&rku[k * GG + UU]);
            float wh = __ldg(&rku[k * GG + 2 * UU]);
            float h0 = hs[0][k];
            float h1 = hs[1][k];
            az0 += h0 * wz; ar0 += h0 * wr; ah0 += h0 * wh;
            az1 += h1 * wz; ar1 += h1 * wr; ah1 += h1 * wh;
        }

        float hn[2];
#pragma unroll
        for (int bb = 0; bb < 2; bb++) {
            size_t row = (size_t)(b0 + bb) * TT + t;
            float xz = xw[row * GG + u];
            float xr = xw[row * GG + UU + u];
            float xh = xw[row * GG + 2 * UU + u];
            float rz = bb ? az1 : az0;
            float rr = bb ? ar1 : ar0;
            float rh = bb ? ah1 : ah0;
            float z  = sigmoidf_(xz + rz);
            float r  = sigmoidf_(xr + rr);
            float hh = tanhf(xh + r * rh);
            float ho = hs[bb][u];
            hn[bb]   = z * ho + (1.f - z) * hh;
        }

        __syncthreads();          // everyone done reading old hs
        hs[0][u] = hn[0];
        hs[1][u] = hn[1];
        __syncthreads();          // new hs visible

        if (out_seq) {
#pragma unroll
            for (int bb = 0; bb < 2; bb++) {
                out_seq[((size_t)(b0 + bb) * TT + t) * (2 * UU) + dir * UU + u] = hn[bb];
            }
        }
    }

    if (out_final) {
        out_final[(size_t)b0 * (2 * UU) + dir * UU + u]       = hs[0][u];
        out_final[(size_t)(b0 + 1) * (2 * UU) + dir * UU + u] = hs[1][u];
    }
}

// ------------------------------------------------------------------
// 4) Output head: logits = h2 @ wout + bout ; softmax over 20 classes
// ------------------------------------------------------------------
__global__ void out_kernel(const float* __restrict__ h2,
                           const float* __restrict__ wout,
                           const float* __restrict__ bout,
                           float* __restrict__ out) {
    int b = blockIdx.x;
    int c = threadIdx.x;   // 32 threads; first 20 compute
    __shared__ float logits[CC];
    if (c < CC) {
        float acc = bout[c];
        const float* hrow = h2 + (size_t)b * (2 * UU);
#pragma unroll 4
        for (int j = 0; j < 2 * UU; j++) acc += hrow[j] * wout[(size_t)j * CC + c];
        logits[c] = acc;
    }
    __syncthreads();
    if (c == 0) {
        float m = logits[0];
#pragma unroll
        for (int i = 1; i < CC; i++) m = fmaxf(m, logits[i]);
        float s = 0.f;
#pragma unroll
        for (int i = 0; i < CC; i++) { float ev = expf(logits[i] - m); logits[i] = ev; s += ev; }
        float inv = 1.f / s;
#pragma unroll
        for (int i = 0; i < CC; i++) out[(size_t)b * CC + i] = logits[i] * inv;
    }
}

// ------------------------------------------------------------------
// Launcher
// ------------------------------------------------------------------
extern "C" void kernel_launch(void* const* d_in, const int* in_sizes, int n_in,
                              void* d_out, int out_size) {
    const int*   x    = (const int*)  d_in[0];
    const float* emb  = (const float*)d_in[1];
    const float* k1f  = (const float*)d_in[2];
    const float* rk1f = (const float*)d_in[3];
    const float* b1f  = (const float*)d_in[4];
    const float* k1b  = (const float*)d_in[5];
    const float* rk1b = (const float*)d_in[6];
    const float* b1b  = (const float*)d_in[7];
    const float* k2f  = (const float*)d_in[8];
    const float* rk2f = (const float*)d_in[9];
    const float* b2f  = (const float*)d_in[10];
    const float* k2b  = (const float*)d_in[11];
    const float* rk2b = (const float*)d_in[12];
    const float* b2b  = (const float*)d_in[13];
    const float* wout = (const float*)d_in[14];
    const float* bout = (const float*)d_in[15];
    float* out = (float*)d_out;

    float *e_p, *xwf_p, *xwb_p, *h1_p, *h2_p;
    cudaGetSymbolAddress((void**)&e_p,   g_e);
    cudaGetSymbolAddress((void**)&xwf_p, g_xwf);
    cudaGetSymbolAddress((void**)&xwb_p, g_xwb);
    cudaGetSymbolAddress((void**)&h1_p,  g_h1);
    cudaGetSymbolAddress((void**)&h2_p,  g_h2);

    const int M = BB * TT;                 // 32768
    dim3 ggrid(GG / GBN, M / GBM);         // (6, 256)

    // 1) embedding gather
    gather_kernel<<<M, 96>>>(x, emb, e_p);

    // 2) layer-1 input projections (bias row 0)
    sgemm_bias<<<ggrid, 256>>>(e_p, k1f, b1f, xwf_p, M, GG, EE);
    sgemm_bias<<<ggrid, 256>>>(e_p, k1b, b1b, xwb_p, M, GG, EE);

    // 3) layer-1 recurrence (bias row 1 = b + G), writes h1 sequence
    gru_layer<<<64, 256>>>(xwf_p, xwb_p, rk1f, rk1b,
                           b1f + GG, b1b + GG, h1_p, nullptr);

    // 4) layer-2 input projections
    sgemm_bias<<<ggrid, 256>>>(h1_p, k2f, b2f, xwf_p, M, GG, 2 * UU);
    sgemm_bias<<<ggrid, 256>>>(h1_p, k2b, b2b, xwb_p, M, GG, 2 * UU);

    // 5) layer-2 recurrence, final states only
    gru_layer<<<64, 256>>>(xwf_p, xwb_p, rk2f, rk2b,
                           b2f + GG, b2b + GG, nullptr, h2_p);

    // 6) output head + softmax
    out_kernel<<<BB, 32>>>(h2_p, wout, bout, out);
}

// round 3
// speedup vs baseline: 4.6588x; 4.6588x over previous
#include <cuda_runtime.h>
#include <cuda_fp16.h>
#include <math.h>

// Problem dims
#define BB 64
#define TT 512
#define EE 300
#define UU 256
#define GG 768
#define CC 20

// ------------------------------------------------------------------
// Scratch (device globals; allocation inside kernel_launch is banned)
// ------------------------------------------------------------------
__device__ float g_e  [BB * TT * EE];       // embedded input  [B*T, 300]
__device__ float g_xwf[BB * TT * GG];       // xw forward      [B*T, 768]
__device__ float g_xwb[BB * TT * GG];       // xw backward     [B*T, 768]
__device__ float g_h1 [BB * TT * 2 * UU];   // layer-1 output  [B*T, 512]
__device__ float g_h2 [BB * 2 * UU];        // layer-2 final   [B, 512]
__device__ __half g_rkh_f[UU * GG];         // fp16 recurrent weights fwd
__device__ __half g_rkh_b[UU * GG];         // fp16 recurrent weights bwd

// ------------------------------------------------------------------
// 0) fp32 -> fp16 weight conversion
// ------------------------------------------------------------------
__global__ void f2h_kernel(const float* __restrict__ in, __half* __restrict__ out, int n) {
    int i = blockIdx.x * blockDim.x + threadIdx.x;
    if (i < n) out[i] = __float2half_rn(in[i]);
}

// ------------------------------------------------------------------
// 1) Embedding gather: e[row, :] = emb[x[row], :]   (300 floats = 75 float4)
// ------------------------------------------------------------------
__global__ void gather_kernel(const int* __restrict__ x,
                              const float* __restrict__ emb,
                              float* __restrict__ e) {
    int row = blockIdx.x;
    int tid = threadIdx.x;
    if (tid < 75) {
        const float4* src = reinterpret_cast<const float4*>(emb + (size_t)x[row] * EE);
        float4*       dst = reinterpret_cast<float4*>(e + (size_t)row * EE);
        dst[tid] = src[tid];
    }
}

// ------------------------------------------------------------------
// 2) SGEMM with bias: C[M,N] = A[M,K] @ Bm[K,N] + bias[N]
// ------------------------------------------------------------------
#define GBM 128
#define GBN 128
#define GBK 8

__global__ __launch_bounds__(256)
void sgemm_bias(const float* __restrict__ A, const float* __restrict__ Bm,
                const float* __restrict__ bias, float* __restrict__ C,
                int M, int N, int K) {
    __shared__ float As[GBK][GBM];
    __shared__ float Bs[GBK][GBN];

    int tid = threadIdx.x;
    int bm = blockIdx.y * GBM;
    int bn = blockIdx.x * GBN;

    int tr = tid / 16;
    int tc = tid % 16;

    int aRow = tid / 2;
    int aCol = (tid % 2) * 4;
    int bRow = tid / 32;
    int bCol = (tid % 32) * 4;

    float acc[8][8];
#pragma unroll
    for (int i = 0; i < 8; i++)
#pragma unroll
        for (int j = 0; j < 8; j++) acc[i][j] = 0.f;

    for (int k0 = 0; k0 < K; k0 += GBK) {
        if (k0 + aCol + 3 < K) {
            float4 v = *reinterpret_cast<const float4*>(&A[(size_t)(bm + aRow) * K + k0 + aCol]);
            As[aCol + 0][aRow] = v.x;
            As[aCol + 1][aRow] = v.y;
            As[aCol + 2][aRow] = v.z;
            As[aCol + 3][aRow] = v.w;
        } else {
#pragma unroll
            for (int i = 0; i < 4; i++) {
                int kk = k0 + aCol + i;
                As[aCol + i][aRow] = (kk < K) ? A[(size_t)(bm + aRow) * K + kk] : 0.f;
            }
        }
        {
            int kk = k0 + bRow;
            if (kk < K) {
                float4 v = *reinterpret_cast<const float4*>(&Bm[(size_t)kk * N + bn + bCol]);
                Bs[bRow][bCol + 0] = v.x;
                Bs[bRow][bCol + 1] = v.y;
                Bs[bRow][bCol + 2] = v.z;
                Bs[bRow][bCol + 3] = v.w;
            } else {
                Bs[bRow][bCol + 0] = 0.f;
                Bs[bRow][bCol + 1] = 0.f;
                Bs[bRow][bCol + 2] = 0.f;
                Bs[bRow][bCol + 3] = 0.f;
            }
        }
        __syncthreads();

#pragma unroll
        for (int k = 0; k < GBK; k++) {
            float a[8], b[8];
#pragma unroll
            for (int i = 0; i < 8; i++) a[i] = As[k][tr * 8 + i];
#pragma unroll
            for (int j = 0; j < 8; j++) b[j] = Bs[k][tc * 8 + j];
#pragma unroll
            for (int i = 0; i < 8; i++)
#pragma unroll
                for (int j = 0; j < 8; j++) acc[i][j] += a[i] * b[j];
        }
        __syncthreads();
    }

#pragma unroll
    for (int i = 0; i < 8; i++) {
#pragma unroll
        for (int j = 0; j < 8; j++) {
            int col = bn + tc * 8 + j;
            C[(size_t)(bm + tr * 8 + i) * N + col] = acc[i][j] + bias[col];
        }
    }
}

// ------------------------------------------------------------------
// 3) GRU recurrence, high-parallelism version.
//    64 CTAs (32 fwd + 32 bwd), each owns 2 batch rows, 768 threads.
//    Thread layout: kq = tid/96 in [0,8) owns k-slice of 32;
//                   gq = tid%96 owns 8 gate columns (float16x8 via LDG.128).
//    Inner products accumulate with packed fma.rn.f32x2 over column pairs.
//    Partials reduced through SMEM; 512 "gate" threads apply nonlinearity.
// ------------------------------------------------------------------
#define KQ 8
#define GQN 96
#define KSL (UU / KQ)   // 32
#define GRU_SMEM (UU * 8 + KQ * 2 * GG * 4)   // hs (float2[256]) + part

__global__ __launch_bounds__(768)
void gru_layer_fast(const float* __restrict__ xw_f, const float* __restrict__ xw_b,
                    const __half* __restrict__ rkh_f, const __half* __restrict__ rkh_b,
                    const float* __restrict__ bin_f, const float* __restrict__ bin_b,
                    float* __restrict__ out_seq,   // [B*T, 512] or nullptr
                    float* __restrict__ out_final) // [B, 512]  or nullptr
{
    extern __shared__ char smem_raw[];
    float2* hs   = reinterpret_cast<float2*>(smem_raw);              // [UU]
    float*  part = reinterpret_cast<float*>(smem_raw + UU * 8);      // [KQ][2][GG]

    int cta  = blockIdx.x;     // 0..63
    int dir  = cta >> 5;       // 0 fwd, 1 bwd
    int pair = cta & 31;
    int b0   = pair * 2;

    const float*  xw  = dir ? xw_b  : xw_f;
    const __half* rkh = dir ? rkh_b : rkh_f;
    const float*  bin = dir ? bin_b : bin_f;

    int tid = threadIdx.x;
    int kq  = tid / GQN;          // 0..7
    int gq  = tid % GQN;          // 0..95
    int g0  = gq * 8;

    for (int i = tid; i < UU; i += blockDim.x) hs[i] = make_float2(0.f, 0.f);

    // gate-phase identity
    const int u  = tid & 255;
    const int gb = (tid >> 8) & 1;
    float bz = 0.f, br = 0.f, bh = 0.f;
    if (tid < 512) { bz = bin[u]; br = bin[UU + u]; bh = bin[2 * UU + u]; }

    const __half* wbase = rkh + (size_t)(kq * KSL) * GG + g0;
    const int kbase = kq * KSL;

    __syncthreads();

    for (int s = 0; s < TT; s++) {
        int t = dir ? (TT - 1 - s) : s;

        // ---- partial inner products over this thread's k-slice ----
        unsigned long long acc[4][2];
#pragma unroll
        for (int c = 0; c < 4; c++) { acc[c][0] = 0ull; acc[c][1] = 0ull; }

#pragma unroll 8
        for (int k = 0; k < KSL; k++) {
            uint4 wv = *reinterpret_cast<const uint4*>(wbase + (size_t)k * GG);
            float2 h01 = hs[kbase + k];
            unsigned long long hp0, hp1;
            asm("mov.b64 %0, {%1, %1};" : "=l"(hp0) : "f"(h01.x));
            asm("mov.b64 %0, {%1, %1};" : "=l"(hp1) : "f"(h01.y));
            unsigned int wr_[4] = {wv.x, wv.y, wv.z, wv.w};
#pragma unroll
            for (int c = 0; c < 4; c++) {
                __half2 wh = *reinterpret_cast<__half2*>(&wr_[c]);
                float2 wf = __half22float2(wh);
                unsigned long long wpk;
                asm("mov.b64 %0, {%1, %2};" : "=l"(wpk) : "f"(wf.x), "f"(wf.y));
                asm("fma.rn.f32x2 %0, %1, %2, %0;" : "+l"(acc[c][0]) : "l"(wpk), "l"(hp0));
                asm("fma.rn.f32x2 %0, %1, %2, %0;" : "+l"(acc[c][1]) : "l"(wpk), "l"(hp1));
            }
        }

        // ---- write partials ----
        float* p0 = part + ((size_t)kq * 2 + 0) * GG + g0;
        float* p1 = part + ((size_t)kq * 2 + 1) * GG + g0;
#pragma unroll
        for (int c = 0; c < 4; c++) {
            float lo0, hi0, lo1, hi1;
            asm("mov.b64 {%0, %1}, %2;" : "=f"(lo0), "=f"(hi0) : "l"(acc[c][0]));
            asm("mov.b64 {%0, %1}, %2;" : "=f"(lo1), "=f"(hi1) : "l"(acc[c][1]));
            p0[2 * c] = lo0; p0[2 * c + 1] = hi0;
            p1[2 * c] = lo1; p1[2 * c + 1] = hi1;
        }
        __syncthreads();

        // ---- gate phase: 512 threads = (batch within pair, unit) ----
        if (tid < 512) {
            float rz = bz, rr = br, rh = bh;
#pragma unroll
            for (int q = 0; q < KQ; q++) {
                const float* pq = part + ((size_t)q * 2 + gb) * GG;
                rz += pq[u];
                rr += pq[UU + u];
                rh += pq[2 * UU + u];
            }
            size_t row = (size_t)(b0 + gb) * TT + t;
            float xz = xw[row * GG + u];
            float xr = xw[row * GG + UU + u];
            float xh = xw[row * GG + 2 * UU + u];
            float z  = 1.f / (1.f + expf(-(xz + rz)));
            float r  = 1.f / (1.f + expf(-(xr + rr)));
            float hh = tanhf(xh + r * rh);
            float ho = gb ? hs[u].y : hs[u].x;
            float hn = z * ho + (1.f - z) * hh;
            if (gb) hs[u].y = hn; else hs[u].x = hn;
            if (out_seq)
                out_seq[row * (2 * UU) + dir * UU + u] = hn;
        }
        __syncthreads();
    }

    if (out_final && tid < 512) {
        float v = gb ? hs[u].y : hs[u].x;
        out_final[(size_t)(b0 + gb) * (2 * UU) + dir * UU + u] = v;
    }
}

// ------------------------------------------------------------------
// 4) Output head: logits = h2 @ wout + bout ; softmax over 20 classes
// ------------------------------------------------------------------
__global__ void out_kernel(const float* __restrict__ h2,
                           const float* __restrict__ wout,
                           const float* __restrict__ bout,
                           float* __restrict__ out) {
    int b = blockIdx.x;
    int c = threadIdx.x;
    __shared__ float logits[CC];
    if (c < CC) {
        float acc = bout[c];
        const float* hrow = h2 + (size_t)b * (2 * UU);
#pragma unroll 4
        for (int j = 0; j < 2 * UU; j++) acc += hrow[j] * wout[(size_t)j * CC + c];
        logits[c] = acc;
    }
    __syncthreads();
    if (c == 0) {
        float m = logits[0];
#pragma unroll
        for (int i = 1; i < CC; i++) m = fmaxf(m, logits[i]);
        float s = 0.f;
#pragma unroll
        for (int i = 0; i < CC; i++) { float ev = expf(logits[i] - m); logits[i] = ev; s += ev; }
        float inv = 1.f / s;
#pragma unroll
        for (int i = 0; i < CC; i++) out[(size_t)b * CC + i] = logits[i] * inv;
    }
}

// ------------------------------------------------------------------
// Launcher
// ------------------------------------------------------------------
extern "C" void kernel_launch(void* const* d_in, const int* in_sizes, int n_in,
                              void* d_out, int out_size) {
    const int*   x    = (const int*)  d_in[0];
    const float* emb  = (const float*)d_in[1];
    const float* k1f  = (const float*)d_in[2];
    const float* rk1f = (const float*)d_in[3];
    const float* b1f  = (const float*)d_in[4];
    const float* k1b  = (const float*)d_in[5];
    const float* rk1b = (const float*)d_in[6];
    const float* b1b  = (const float*)d_in[7];
    const float* k2f  = (const float*)d_in[8];
    const float* rk2f = (const float*)d_in[9];
    const float* b2f  = (const float*)d_in[10];
    const float* k2b  = (const float*)d_in[11];
    const float* rk2b = (const float*)d_in[12];
    const float* b2b  = (const float*)d_in[13];
    const float* wout = (const float*)d_in[14];
    const float* bout = (const float*)d_in[15];
    float* out = (float*)d_out;

    float *e_p, *xwf_p, *xwb_p, *h1_p, *h2_p;
    __half *rkhf_p, *rkhb_p;
    cudaGetSymbolAddress((void**)&e_p,    g_e);
    cudaGetSymbolAddress((void**)&xwf_p,  g_xwf);
    cudaGetSymbolAddress((void**)&xwb_p,  g_xwb);
    cudaGetSymbolAddress((void**)&h1_p,   g_h1);
    cudaGetSymbolAddress((void**)&h2_p,   g_h2);
    cudaGetSymbolAddress((void**)&rkhf_p, g_rkh_f);
    cudaGetSymbolAddress((void**)&rkhb_p, g_rkh_b);

    cudaFuncSetAttribute(gru_layer_fast,
                         cudaFuncAttributeMaxDynamicSharedMemorySize, GRU_SMEM);

    const int M = BB * TT;                 // 32768
    dim3 ggrid(GG / GBN, M / GBM);         // (6, 256)
    const int RKN = UU * GG;               // 196608

    // 1) embedding gather
    gather_kernel<<<M, 96>>>(x, emb, e_p);

    // 2) layer-1 input projections
    sgemm_bias<<<ggrid, 256>>>(e_p, k1f, b1f, xwf_p, M, GG, EE);
    sgemm_bias<<<ggrid, 256>>>(e_p, k1b, b1b, xwb_p, M, GG, EE);

    // 2b) convert layer-1 recurrent weights to fp16
    f2h_kernel<<<(RKN + 1023) / 1024, 1024>>>(rk1f, rkhf_p, RKN);
    f2h_kernel<<<(RKN + 1023) / 1024, 1024>>>(rk1b, rkhb_p, RKN);

    // 3) layer-1 recurrence
    gru_layer_fast<<<64, 768, GRU_SMEM>>>(xwf_p, xwb_p, rkhf_p, rkhb_p,
                                          b1f + GG, b1b + GG, h1_p, nullptr);

    // 4) layer-2 input projections
    sgemm_bias<<<ggrid, 256>>>(h1_p, k2f, b2f, xwf_p, M, GG, 2 * UU);
    sgemm_bias<<<ggrid, 256>>>(h1_p, k2b, b2b, xwb_p, M, GG, 2 * UU);

    // 4b) convert layer-2 recurrent weights to fp16
    f2h_kernel<<<(RKN + 1023) / 1024, 1024>>>(rk2f, rkhf_p, RKN);
    f2h_kernel<<<(RKN + 1023) / 1024, 1024>>>(rk2b, rkhb_p, RKN);

    // 5) layer-2 recurrence, final states only
    gru_layer_fast<<<64, 768, GRU_SMEM>>>(xwf_p, xwb_p, rkhf_p, rkhb_p,
                                          b2f + GG, b2b + GG, nullptr, h2_p);

    // 6) output head + softmax
    out_kernel<<<BB, 32>>>(h2_p, wout, bout, out);
}

// round 4
// speedup vs baseline: 6.1359x; 1.3171x over previous
#include <cuda_runtime.h>
#include <cuda_fp16.h>
#include <math.h>
#include <stdint.h>

// Problem dims
#define BB 64
#define TT 512
#define EE 300
#define KE 320          // padded embedding K (multiple of 32)
#define UU 256
#define GG 768
#define CC 20

// ------------------------------------------------------------------
// Scratch (device globals; allocation inside kernel_launch is banned)
// ------------------------------------------------------------------
__device__ __half g_eh  [BB * TT * KE];      // fp16 embedded input [B*T, 320]
__device__ __half g_h1h [BB * TT * 2 * UU];  // fp16 layer-1 output [B*T, 512]
__device__ float  g_xwf [BB * TT * GG];      // xw forward  [B*T, 768] fp32
__device__ float  g_xwb [BB * TT * GG];      // xw backward [B*T, 768] fp32
__device__ float  g_h2  [BB * 2 * UU];       // layer-2 final [B, 512]
__device__ __half g_rkh_f[UU * GG];          // fp16 recurrent weights fwd
__device__ __half g_rkh_b[UU * GG];          // fp16 recurrent weights bwd
__device__ __half g_w1hf[KE * GG];           // fp16 padded k1f
__device__ __half g_w1hb[KE * GG];           // fp16 padded k1b
__device__ __half g_w2hf[2 * UU * GG];       // fp16 k2f
__device__ __half g_w2hb[2 * UU * GG];       // fp16 k2b

// ------------------------------------------------------------------
// 0) fp32 -> fp16 conversions
// ------------------------------------------------------------------
__global__ void f2h_kernel(const float* __restrict__ in, __half* __restrict__ out, int n) {
    int i = blockIdx.x * blockDim.x + threadIdx.x;
    if (i < n) out[i] = __float2half_rn(in[i]);
}

// pad rows: in [rows_in][cols] -> out [rows_out][cols], zero-filled tail rows
__global__ void f2h_pad_kernel(const float* __restrict__ in, __half* __restrict__ out,
                               int rows_in, int rows_out, int cols) {
    int i = blockIdx.x * blockDim.x + threadIdx.x;
    if (i < rows_out * cols) {
        int r = i / cols;
        out[i] = (r < rows_in) ? __float2half_rn(in[i]) : __half(0.f);
    }
}

// ------------------------------------------------------------------
// 1) Embedding gather straight to fp16, K padded to 320
// ------------------------------------------------------------------
__global__ void gather_h_kernel(const int* __restrict__ x,
                                const float* __restrict__ emb,
                                __half* __restrict__ eh) {
    int row = blockIdx.x;
    int t = threadIdx.x;            // 160 threads, each one half2
    const float* src = emb + (size_t)x[row] * EE;
    __half2* dst = reinterpret_cast<__half2*>(eh + (size_t)row * KE);
    if (t < EE / 2) {
        float2 v = *reinterpret_cast<const float2*>(src + 2 * t);
        dst[t] = __floats2half2_rn(v.x, v.y);
    } else if (t < KE / 2) {
        dst[t] = __floats2half2_rn(0.f, 0.f);
    }
}

// ------------------------------------------------------------------
// 2) HGEMM with bias (tensor cores): C[M,768] = A[M,K]h @ Bw[K,768]h + bias
//    Block 128x128, BK=32, 8 warps, warp tile 64x32 via mma.m16n8k16.
//    Requires M%128==0, K%32==0.
// ------------------------------------------------------------------
#define SA 56    // As row stride in halves (112B: 16B-aligned, conflict-free LDSM)
#define SB 136   // Bs row stride in halves (272B)

__device__ __forceinline__ void ldsm_x4(uint32_t& r0, uint32_t& r1, uint32_t& r2, uint32_t& r3,
                                        uint32_t addr) {
    asm volatile("ldmatrix.sync.aligned.m8n8.x4.shared.b16 {%0,%1,%2,%3}, [%4];"
                 : "=r"(r0), "=r"(r1), "=r"(r2), "=r"(r3) : "r"(addr));
}
__device__ __forceinline__ void ldsm_x4_t(uint32_t& r0, uint32_t& r1, uint32_t& r2, uint32_t& r3,
                                          uint32_t addr) {
    asm volatile("ldmatrix.sync.aligned.m8n8.x4.trans.shared.b16 {%0,%1,%2,%3}, [%4];"
                 : "=r"(r0), "=r"(r1), "=r"(r2), "=r"(r3) : "r"(addr));
}
__device__ __forceinline__ void mma16816(float* c, const uint32_t* a, const uint32_t* b) {
    asm volatile("mma.sync.aligned.m16n8k16.row.col.f32.f16.f16.f32 "
                 "{%0,%1,%2,%3}, {%4,%5,%6,%7}, {%8,%9}, {%0,%1,%2,%3};"
                 : "+f"(c[0]), "+f"(c[1]), "+f"(c[2]), "+f"(c[3])
                 : "r"(a[0]), "r"(a[1]), "r"(a[2]), "r"(a[3]), "r"(b[0]), "r"(b[1]));
}

__global__ __launch_bounds__(256)
void hgemm_bias(const __half* __restrict__ A, const __half* __restrict__ Bw,
                const float* __restrict__ bias, float* __restrict__ C,
                int K, int lda) {
    __shared__ __half As[128 * SA];
    __shared__ __half Bs[32 * SB];

    int tid  = threadIdx.x;
    int w    = tid >> 5;
    int lane = tid & 31;
    int bm   = blockIdx.y * 128;
    int bn   = blockIdx.x * 128;
    int wm   = (w >> 2) * 64;   // 0 or 64
    int wn   = (w & 3) * 32;    // 0,32,64,96

    float acc[4][4][4];
#pragma unroll
    for (int mi = 0; mi < 4; mi++)
#pragma unroll
        for (int ni = 0; ni < 4; ni++)
#pragma unroll
            for (int c = 0; c < 4; c++) acc[mi][ni][c] = 0.f;

    int arow = tid >> 1, acol = (tid & 1) * 16;
    int brow = tid >> 3, bcol = (tid & 7) * 16;
    const __half* Ag = A + (size_t)(bm + arow) * lda + acol;
    const __half* Bg = Bw + (size_t)brow * GG + bn + bcol;

    // LDSM source addresses (fixed per thread)
    uint32_t a_addr[4], b_addr[2];
#pragma unroll
    for (int mi = 0; mi < 4; mi++) {
        int m  = wm + mi * 16 + (lane & 15);
        int kc = (lane >> 4) * 8;
        a_addr[mi] = (uint32_t)__cvta_generic_to_shared(&As[m * SA + kc]);
    }
#pragma unroll
    for (int nj = 0; nj < 2; nj++) {
        int kr = lane & 15;
        int nc = wn + nj * 16 + (lane >> 4) * 8;
        b_addr[nj] = (uint32_t)__cvta_generic_to_shared(&Bs[kr * SB + nc]);
    }

    for (int k0 = 0; k0 < K; k0 += 32) {
        *reinterpret_cast<uint4*>(&As[arow * SA + acol])     = *reinterpret_cast<const uint4*>(Ag);
        *reinterpret_cast<uint4*>(&As[arow * SA + acol + 8]) = *reinterpret_cast<const uint4*>(Ag + 8);
        *reinterpret_cast<uint4*>(&Bs[brow * SB + bcol])     = *reinterpret_cast<const uint4*>(Bg);
        *reinterpret_cast<uint4*>(&Bs[brow * SB + bcol + 8]) = *reinterpret_cast<const uint4*>(Bg + 8);
        Ag += 32;
        Bg += (size_t)32 * GG;
        __syncthreads();

#pragma unroll
        for (int kk = 0; kk < 2; kk++) {
            uint32_t afr[4][4];
            uint32_t bfr[4][2];
#pragma unroll
            for (int mi = 0; mi < 4; mi++)
                ldsm_x4(afr[mi][0], afr[mi][1], afr[mi][2], afr[mi][3],
                        a_addr[mi] + kk * 16 * 2);
#pragma unroll
            for (int nj = 0; nj < 2; nj++) {
                uint32_t r0, r1, r2, r3;
                ldsm_x4_t(r0, r1, r2, r3, b_addr[nj] + kk * 16 * SB * 2);
                bfr[2 * nj][0] = r0; bfr[2 * nj][1] = r1;
                bfr[2 * nj + 1][0] = r2; bfr[2 * nj + 1][1] = r3;
            }
#pragma unroll
            for (int mi = 0; mi < 4; mi++)
#pragma unroll
                for (int ni = 0; ni < 4; ni++)
                    mma16816(acc[mi][ni], afr[mi], bfr[ni]);
        }
        __syncthreads();
    }

    // epilogue: fp32 + bias
#pragma unroll
    for (int mi = 0; mi < 4; mi++) {
#pragma unroll
        for (int ni = 0; ni < 4; ni++) {
            int r0 = bm + wm + mi * 16 + (lane >> 2);
            int c0 = bn + wn + ni * 8 + (lane & 3) * 2;
            float bv0 = bias[c0], bv1 = bias[c0 + 1];
            float* p0 = C + (size_t)r0 * GG + c0;
            float* p1 = C + (size_t)(r0 + 8) * GG + c0;
            p0[0] = acc[mi][ni][0] + bv0;
            p0[1] = acc[mi][ni][1] + bv1;
            p1[0] = acc[mi][ni][2] + bv0;
            p1[1] = acc[mi][ni][3] + bv1;
        }
    }
}

// ------------------------------------------------------------------
// 3) GRU recurrence (unchanged from R2 except fp16 out_seq)
// ------------------------------------------------------------------
#define KQ 8
#define GQN 96
#define KSL (UU / KQ)   // 32
#define GRU_SMEM (UU * 8 + KQ * 2 * GG * 4)

__global__ __launch_bounds__(768)
void gru_layer_fast(const float* __restrict__ xw_f, const float* __restrict__ xw_b,
                    const __half* __restrict__ rkh_f, const __half* __restrict__ rkh_b,
                    const float* __restrict__ bin_f, const float* __restrict__ bin_b,
                    __half* __restrict__ out_seq,  // [B*T, 512] fp16 or nullptr
                    float* __restrict__ out_final) // [B, 512]  or nullptr
{
    extern __shared__ char smem_raw[];
    float2* hs   = reinterpret_cast<float2*>(smem_raw);              // [UU]
    float*  part = reinterpret_cast<float*>(smem_raw + UU * 8);      // [KQ][2][GG]

    int cta  = blockIdx.x;     // 0..63
    int dir  = cta >> 5;
    int pair = cta & 31;
    int b0   = pair * 2;

    const float*  xw  = dir ? xw_b  : xw_f;
    const __half* rkh = dir ? rkh_b : rkh_f;
    const float*  bin = dir ? bin_b : bin_f;

    int tid = threadIdx.x;
    int kq  = tid / GQN;
    int gq  = tid % GQN;
    int g0  = gq * 8;

    for (int i = tid; i < UU; i += blockDim.x) hs[i] = make_float2(0.f, 0.f);

    const int u  = tid & 255;
    const int gb = (tid >> 8) & 1;
    float bz = 0.f, br = 0.f, bh = 0.f;
    if (tid < 512) { bz = bin[u]; br = bin[UU + u]; bh = bin[2 * UU + u]; }

    const __half* wbase = rkh + (size_t)(kq * KSL) * GG + g0;
    const int kbase = kq * KSL;

    __syncthreads();

    for (int s = 0; s < TT; s++) {
        int t = dir ? (TT - 1 - s) : s;

        unsigned long long acc[4][2];
#pragma unroll
        for (int c = 0; c < 4; c++) { acc[c][0] = 0ull; acc[c][1] = 0ull; }

#pragma unroll 8
        for (int k = 0; k < KSL; k++) {
            uint4 wv = *reinterpret_cast<const uint4*>(wbase + (size_t)k * GG);
            float2 h01 = hs[kbase + k];
            unsigned long long hp0, hp1;
            asm("mov.b64 %0, {%1, %1};" : "=l"(hp0) : "f"(h01.x));
            asm("mov.b64 %0, {%1, %1};" : "=l"(hp1) : "f"(h01.y));
            unsigned int wr_[4] = {wv.x, wv.y, wv.z, wv.w};
#pragma unroll
            for (int c = 0; c < 4; c++) {
                __half2 wh = *reinterpret_cast<__half2*>(&wr_[c]);
                float2 wf = __half22float2(wh);
                unsigned long long wpk;
                asm("mov.b64 %0, {%1, %2};" : "=l"(wpk) : "f"(wf.x), "f"(wf.y));
                asm("fma.rn.f32x2 %0, %1, %2, %0;" : "+l"(acc[c][0]) : "l"(wpk), "l"(hp0));
                asm("fma.rn.f32x2 %0, %1, %2, %0;" : "+l"(acc[c][1]) : "l"(wpk), "l"(hp1));
            }
        }

        float* p0 = part + ((size_t)kq * 2 + 0) * GG + g0;
        float* p1 = part + ((size_t)kq * 2 + 1) * GG + g0;
#pragma unroll
        for (int c = 0; c < 4; c++) {
            float lo0, hi0, lo1, hi1;
            asm("mov.b64 {%0, %1}, %2;" : "=f"(lo0), "=f"(hi0) : "l"(acc[c][0]));
            asm("mov.b64 {%0, %1}, %2;" : "=f"(lo1), "=f"(hi1) : "l"(acc[c][1]));
            p0[2 * c] = lo0; p0[2 * c + 1] = hi0;
            p1[2 * c] = lo1; p1[2 * c + 1] = hi1;
        }
        __syncthreads();

        if (tid < 512) {
            float rz = bz, rr = br, rh = bh;
#pragma unroll
            for (int q = 0; q < KQ; q++) {
                const float* pq = part + ((size_t)q * 2 + gb) * GG;
                rz += pq[u];
                rr += pq[UU + u];
                rh += pq[2 * UU + u];
            }
            size_t row = (size_t)(b0 + gb) * TT + t;
            float xz = xw[row * GG + u];
            float xr = xw[row * GG + UU + u];
            float xh = xw[row * GG + 2 * UU + u];
            float z  = 1.f / (1.f + expf(-(xz + rz)));
            float r  = 1.f / (1.f + expf(-(xr + rr)));
            float hh = tanhf(xh + r * rh);
            float ho = gb ? hs[u].y : hs[u].x;
            float hn = z * ho + (1.f - z) * hh;
            if (gb) hs[u].y = hn; else hs[u].x = hn;
            if (out_seq)
                out_seq[row * (2 * UU) + dir * UU + u] = __float2half_rn(hn);
        }
        __syncthreads();
    }

    if (out_final && tid < 512) {
        float v = gb ? hs[u].y : hs[u].x;
        out_final[(size_t)(b0 + gb) * (2 * UU) + dir * UU + u] = v;
    }
}

// ------------------------------------------------------------------
// 4) Output head
// ------------------------------------------------------------------
__global__ void out_kernel(const float* __restrict__ h2,
                           const float* __restrict__ wout,
                           const float* __restrict__ bout,
                           float* __restrict__ out) {
    int b = blockIdx.x;
    int c = threadIdx.x;
    __shared__ float logits[CC];
    if (c < CC) {
        float acc = bout[c];
        const float* hrow = h2 + (size_t)b * (2 * UU);
#pragma unroll 4
        for (int j = 0; j < 2 * UU; j++) acc += hrow[j] * wout[(size_t)j * CC + c];
        logits[c] = acc;
    }
    __syncthreads();
    if (c == 0) {
        float m = logits[0];
#pragma unroll
        for (int i = 1; i < CC; i++) m = fmaxf(m, logits[i]);
        float s = 0.f;
#pragma unroll
        for (int i = 0; i < CC; i++) { float ev = expf(logits[i] - m); logits[i] = ev; s += ev; }
        float inv = 1.f / s;
#pragma unroll
        for (int i = 0; i < CC; i++) out[(size_t)b * CC + i] = logits[i] * inv;
    }
}

// ------------------------------------------------------------------
// Launcher
// ------------------------------------------------------------------
extern "C" void kernel_launch(void* const* d_in, const int* in_sizes, int n_in,
                              void* d_out, int out_size) {
    const int*   x    = (const int*)  d_in[0];
    const float* emb  = (const float*)d_in[1];
    const float* k1f  = (const float*)d_in[2];
    const float* rk1f = (const float*)d_in[3];
    const float* b1f  = (const float*)d_in[4];
    const float* k1b  = (const float*)d_in[5];
    const float* rk1b = (const float*)d_in[6];
    const float* b1b  = (const float*)d_in[7];
    const float* k2f  = (const float*)d_in[8];
    const float* rk2f = (const float*)d_in[9];
    const float* b2f  = (const float*)d_in[10];
    const float* k2b  = (const float*)d_in[11];
    const float* rk2b = (const float*)d_in[12];
    const float* b2b  = (const float*)d_in[13];
    const float* wout = (const float*)d_in[14];
    const float* bout = (const float*)d_in[15];
    float* out = (float*)d_out;

    __half *eh_p, *h1h_p, *rkhf_p, *rkhb_p, *w1hf_p, *w1hb_p, *w2hf_p, *w2hb_p;
    float *xwf_p, *xwb_p, *h2_p;
    cudaGetSymbolAddress((void**)&eh_p,   g_eh);
    cudaGetSymbolAddress((void**)&h1h_p,  g_h1h);
    cudaGetSymbolAddress((void**)&xwf_p,  g_xwf);
    cudaGetSymbolAddress((void**)&xwb_p,  g_xwb);
    cudaGetSymbolAddress((void**)&h2_p,   g_h2);
    cudaGetSymbolAddress((void**)&rkhf_p, g_rkh_f);
    cudaGetSymbolAddress((void**)&rkhb_p, g_rkh_b);
    cudaGetSymbolAddress((void**)&w1hf_p, g_w1hf);
    cudaGetSymbolAddress((void**)&w1hb_p, g_w1hb);
    cudaGetSymbolAddress((void**)&w2hf_p, g_w2hf);
    cudaGetSymbolAddress((void**)&w2hb_p, g_w2hb);

    cudaFuncSetAttribute(gru_layer_fast,
                         cudaFuncAttributeMaxDynamicSharedMemorySize, GRU_SMEM);

    const int M = BB * TT;               // 32768
    dim3 hgrid(GG / 128, M / 128);       // (6, 256)
    const int RKN = UU * GG;

    // 0) weight conversions (independent of data path)
    f2h_pad_kernel<<<(KE * GG + 1023) / 1024, 1024>>>(k1f, w1hf_p, EE, KE, GG);
    f2h_pad_kernel<<<(KE * GG + 1023) / 1024, 1024>>>(k1b, w1hb_p, EE, KE, GG);
    f2h_kernel<<<(2 * UU * GG + 1023) / 1024, 1024>>>(k2f, w2hf_p, 2 * UU * GG);
    f2h_kernel<<<(2 * UU * GG + 1023) / 1024, 1024>>>(k2b, w2hb_p, 2 * UU * GG);
    f2h_kernel<<<(RKN + 1023) / 1024, 1024>>>(rk1f, rkhf_p, RKN);
    f2h_kernel<<<(RKN + 1023) / 1024, 1024>>>(rk1b, rkhb_p, RKN);

    // 1) embedding gather -> fp16 padded
    gather_h_kernel<<<M, 160>>>(x, emb, eh_p);

    // 2) layer-1 input projections (tensor cores)
    hgemm_bias<<<hgrid, 256>>>(eh_p, w1hf_p, b1f, xwf_p, KE, KE);
    hgemm_bias<<<hgrid, 256>>>(eh_p, w1hb_p, b1b, xwb_p, KE, KE);

    // 3) layer-1 recurrence -> fp16 h1
    gru_layer_fast<<<64, 768, GRU_SMEM>>>(xwf_p, xwb_p, rkhf_p, rkhb_p,
                                          b1f + GG, b1b + GG, h1h_p, nullptr);

    // 3b) layer-2 recurrent weight conversion (reuse buffers)
    f2h_kernel<<<(RKN + 1023) / 1024, 1024>>>(rk2f, rkhf_p, RKN);
    f2h_kernel<<<(RKN + 1023) / 1024, 1024>>>(rk2b, rkhb_p, RKN);

    // 4) layer-2 input projections
    hgemm_bias<<<hgrid, 256>>>(h1h_p, w2hf_p, b2f, xwf_p, 2 * UU, 2 * UU);
    hgemm_bias<<<hgrid, 256>>>(h1h_p, w2hb_p, b2b, xwb_p, 2 * UU, 2 * UU);

    // 5) layer-2 recurrence, final states only
    gru_layer_fast<<<64, 768, GRU_SMEM>>>(xwf_p, xwb_p, rkhf_p, rkhb_p,
                                          b2f + GG, b2b + GG, nullptr, h2_p);

    // 6) output head + softmax
    out_kernel<<<BB, 32>>>(h2_p, wout, bout, out);
}

// round 5
// speedup vs baseline: 13.1459x; 2.1424x over previous
#include <cuda_runtime.h>
#include <cuda_fp16.h>
#include <math.h>
#include <stdint.h>

// Problem dims
#define BB 64
#define TT 512
#define EE 300
#define KE 320          // padded embedding K (multiple of 32)
#define UU 256
#define GG 768
#define CC 20

// ------------------------------------------------------------------
// Scratch (device globals; allocation inside kernel_launch is banned)
// ------------------------------------------------------------------
__device__ __half g_eh  [BB * TT * KE];      // fp16 embedded input [B*T, 320]
__device__ __half g_h1h [BB * TT * 2 * UU];  // fp16 layer-1 output [B*T, 512]
__device__ float  g_xwf [BB * TT * GG];      // xw forward  [B*T, 768] fp32
__device__ float  g_xwb [BB * TT * GG];      // xw backward [B*T, 768] fp32
__device__ float  g_h2  [BB * 2 * UU];       // layer-2 final [B, 512]
__device__ __half g_rkh_f[UU * GG];          // fp16 recurrent weights fwd
__device__ __half g_rkh_b[UU * GG];          // fp16 recurrent weights bwd
__device__ __half g_w1hf[KE * GG];           // fp16 padded k1f
__device__ __half g_w1hb[KE * GG];           // fp16 padded k1b
__device__ __half g_w2hf[2 * UU * GG];       // fp16 k2f
__device__ __half g_w2hb[2 * UU * GG];       // fp16 k2b

// ------------------------------------------------------------------
// 0) fp32 -> fp16 conversions
// ------------------------------------------------------------------
__global__ void f2h_kernel(const float* __restrict__ in, __half* __restrict__ out, int n) {
    int i = blockIdx.x * blockDim.x + threadIdx.x;
    if (i < n) out[i] = __float2half_rn(in[i]);
}

__global__ void f2h_pad_kernel(const float* __restrict__ in, __half* __restrict__ out,
                               int rows_in, int rows_out, int cols) {
    int i = blockIdx.x * blockDim.x + threadIdx.x;
    if (i < rows_out * cols) {
        int r = i / cols;
        out[i] = (r < rows_in) ? __float2half_rn(in[i]) : __half(0.f);
    }
}

// ------------------------------------------------------------------
// 1) Embedding gather straight to fp16, K padded to 320
// ------------------------------------------------------------------
__global__ void gather_h_kernel(const int* __restrict__ x,
                                const float* __restrict__ emb,
                                __half* __restrict__ eh) {
    int row = blockIdx.x;
    int t = threadIdx.x;
    const float* src = emb + (size_t)x[row] * EE;
    __half2* dst = reinterpret_cast<__half2*>(eh + (size_t)row * KE);
    if (t < EE / 2) {
        float2 v = *reinterpret_cast<const float2*>(src + 2 * t);
        dst[t] = __floats2half2_rn(v.x, v.y);
    } else if (t < KE / 2) {
        dst[t] = __floats2half2_rn(0.f, 0.f);
    }
}

// ------------------------------------------------------------------
// mma/ldmatrix primitives (validated in R4)
// ------------------------------------------------------------------
__device__ __forceinline__ void ldsm_x4(uint32_t& r0, uint32_t& r1, uint32_t& r2, uint32_t& r3,
                                        uint32_t addr) {
    asm volatile("ldmatrix.sync.aligned.m8n8.x4.shared.b16 {%0,%1,%2,%3}, [%4];"
                 : "=r"(r0), "=r"(r1), "=r"(r2), "=r"(r3) : "r"(addr));
}
__device__ __forceinline__ void ldsm_x4_t(uint32_t& r0, uint32_t& r1, uint32_t& r2, uint32_t& r3,
                                          uint32_t addr) {
    asm volatile("ldmatrix.sync.aligned.m8n8.x4.trans.shared.b16 {%0,%1,%2,%3}, [%4];"
                 : "=r"(r0), "=r"(r1), "=r"(r2), "=r"(r3) : "r"(addr));
}
__device__ __forceinline__ void mma16816(float* c, const uint32_t* a, const uint32_t* b) {
    asm volatile("mma.sync.aligned.m16n8k16.row.col.f32.f16.f16.f32 "
                 "{%0,%1,%2,%3}, {%4,%5,%6,%7}, {%8,%9}, {%0,%1,%2,%3};"
                 : "+f"(c[0]), "+f"(c[1]), "+f"(c[2]), "+f"(c[3])
                 : "r"(a[0]), "r"(a[1]), "r"(a[2]), "r"(a[3]), "r"(b[0]), "r"(b[1]));
}

// ------------------------------------------------------------------
// 2) HGEMM with bias (unchanged from R4)
// ------------------------------------------------------------------
#define SA 56
#define SB 136

__global__ __launch_bounds__(256)
void hgemm_bias(const __half* __restrict__ A, const __half* __restrict__ Bw,
                const float* __restrict__ bias, float* __restrict__ C,
                int K, int lda) {
    __shared__ __half As[128 * SA];
    __shared__ __half Bs[32 * SB];

    int tid  = threadIdx.x;
    int w    = tid >> 5;
    int lane = tid & 31;
    int bm   = blockIdx.y * 128;
    int bn   = blockIdx.x * 128;
    int wm   = (w >> 2) * 64;
    int wn   = (w & 3) * 32;

    float acc[4][4][4];
#pragma unroll
    for (int mi = 0; mi < 4; mi++)
#pragma unroll
        for (int ni = 0; ni < 4; ni++)
#pragma unroll
            for (int c = 0; c < 4; c++) acc[mi][ni][c] = 0.f;

    int arow = tid >> 1, acol = (tid & 1) * 16;
    int brow = tid >> 3, bcol = (tid & 7) * 16;
    const __half* Ag = A + (size_t)(bm + arow) * lda + acol;
    const __half* Bg = Bw + (size_t)brow * GG + bn + bcol;

    uint32_t a_addr[4], b_addr[2];
#pragma unroll
    for (int mi = 0; mi < 4; mi++) {
        int m  = wm + mi * 16 + (lane & 15);
        int kc = (lane >> 4) * 8;
        a_addr[mi] = (uint32_t)__cvta_generic_to_shared(&As[m * SA + kc]);
    }
#pragma unroll
    for (int nj = 0; nj < 2; nj++) {
        int kr = lane & 15;
        int nc = wn + nj * 16 + (lane >> 4) * 8;
        b_addr[nj] = (uint32_t)__cvta_generic_to_shared(&Bs[kr * SB + nc]);
    }

    for (int k0 = 0; k0 < K; k0 += 32) {
        *reinterpret_cast<uint4*>(&As[arow * SA + acol])     = *reinterpret_cast<const uint4*>(Ag);
        *reinterpret_cast<uint4*>(&As[arow * SA + acol + 8]) = *reinterpret_cast<const uint4*>(Ag + 8);
        *reinterpret_cast<uint4*>(&Bs[brow * SB + bcol])     = *reinterpret_cast<const uint4*>(Bg);
        *reinterpret_cast<uint4*>(&Bs[brow * SB + bcol + 8]) = *reinterpret_cast<const uint4*>(Bg + 8);
        Ag += 32;
        Bg += (size_t)32 * GG;
        __syncthreads();

#pragma unroll
        for (int kk = 0; kk < 2; kk++) {
            uint32_t afr[4][4];
            uint32_t bfr[4][2];
#pragma unroll
            for (int mi = 0; mi < 4; mi++)
                ldsm_x4(afr[mi][0], afr[mi][1], afr[mi][2], afr[mi][3],
                        a_addr[mi] + kk * 16 * 2);
#pragma unroll
            for (int nj = 0; nj < 2; nj++) {
                uint32_t r0, r1, r2, r3;
                ldsm_x4_t(r0, r1, r2, r3, b_addr[nj] + kk * 16 * SB * 2);
                bfr[2 * nj][0] = r0; bfr[2 * nj][1] = r1;
                bfr[2 * nj + 1][0] = r2; bfr[2 * nj + 1][1] = r3;
            }
#pragma unroll
            for (int mi = 0; mi < 4; mi++)
#pragma unroll
                for (int ni = 0; ni < 4; ni++)
                    mma16816(acc[mi][ni], afr[mi], bfr[ni]);
        }
        __syncthreads();
    }

#pragma unroll
    for (int mi = 0; mi < 4; mi++) {
#pragma unroll
        for (int ni = 0; ni < 4; ni++) {
            int r0 = bm + wm + mi * 16 + (lane >> 2);
            int c0 = bn + wn + ni * 8 + (lane & 3) * 2;
            float bv0 = bias[c0], bv1 = bias[c0 + 1];
            float* p0 = C + (size_t)r0 * GG + c0;
            float* p1 = C + (size_t)(r0 + 8) * GG + c0;
            p0[0] = acc[mi][ni][0] + bv0;
            p0[1] = acc[mi][ni][1] + bv1;
            p1[0] = acc[mi][ni][2] + bv0;
            p1[1] = acc[mi][ni][3] + bv1;
        }
    }
}

// ------------------------------------------------------------------
// 3) GRU recurrence: cluster(8) + SMEM-resident weights + tensor cores.
//    Grid 128 CTAs = 16 clusters of 8. cluster = (dir, batch-group of 8).
//    CTA rank r owns 32 hidden units -> 96 gate cols, all 8 batches.
//    Per step: mma([16(8 used),256]@[256,96]) on warps 0-5; gate phase on
//    all 256 threads (warp=batch, lane=unit); h broadcast to 8 CTAs via
//    DSMEM; one cluster barrier per step.
// ------------------------------------------------------------------
#define CLS 8
#define W_STRIDE 104            // halves; 208B rows, 16B aligned
#define H_STRIDE 264            // halves; 528B rows, 16B aligned
#define GT_STRIDE 100           // floats
#define OFF_W 0
#define OFF_H (256 * W_STRIDE * 2)
#define OFF_G (OFF_H + 2 * 16 * H_STRIDE * 2)
#define GRU_SMEM2 (OFF_G + 8 * GT_STRIDE * 4)

__device__ __forceinline__ void st_cluster_u32(uint32_t laddr, uint32_t rnk, uint32_t v) {
    uint32_t ra;
    asm volatile("mapa.shared::cluster.u32 %0, %1, %2;" : "=r"(ra) : "r"(laddr), "r"(rnk));
    asm volatile("st.shared::cluster.u32 [%0], %1;" :: "r"(ra), "r"(v));
}
__device__ __forceinline__ void cluster_sync_() {
    asm volatile("barrier.cluster.arrive.aligned;" ::: "memory");
    asm volatile("barrier.cluster.wait.aligned;" ::: "memory");
}

__global__ __launch_bounds__(256) __cluster_dims__(CLS, 1, 1)
void gru_cluster(const float* __restrict__ xw_f, const float* __restrict__ xw_b,
                 const __half* __restrict__ rkh_f, const __half* __restrict__ rkh_b,
                 const float* __restrict__ bin_f, const float* __restrict__ bin_b,
                 __half* __restrict__ out_seq,   // [B*T, 512] fp16 or nullptr
                 float* __restrict__ out_final)  // [B, 512] or nullptr
{
    extern __shared__ char sm[];
    __half* wsm  = reinterpret_cast<__half*>(sm + OFF_W);   // [256][W_STRIDE]
    __half* hbuf = reinterpret_cast<__half*>(sm + OFF_H);   // [2][16][H_STRIDE]
    float*  gt   = reinterpret_cast<float*>(sm + OFF_G);    // [8][GT_STRIDE]
    uint32_t smb = (uint32_t)__cvta_generic_to_shared(sm);

    int tid = threadIdx.x;
    int lane = tid & 31;
    int wp = tid >> 5;          // gate phase: wp = batch-in-group
    uint32_t rank;
    asm("mov.u32 %0, %%cluster_ctarank;" : "=r"(rank));
    int cl  = blockIdx.x / CLS;
    int dir = cl >> 3;
    int bg  = cl & 7;

    const float*  xw  = dir ? xw_b  : xw_f;
    const __half* rkh = dir ? rkh_b : rkh_f;
    const float*  bin = dir ? bin_b : bin_f;

    // one-time: load this CTA's 96 weight cols, zero h buffers
    for (int i = tid; i < 256 * 96; i += 256) {
        int k = i / 96, j = i % 96;
        int gcol = (j >> 5) * 256 + (rank << 5) + (j & 31);
        wsm[k * W_STRIDE + j] = rkh[(size_t)k * GG + gcol];
    }
    for (int i = tid; i < 2 * 16 * H_STRIDE; i += 256) hbuf[i] = __half(0.f);

    const int ug = (rank << 5) + lane;           // global unit for gate phase
    const float bz = bin[ug];
    const float br = bin[UU + ug];
    const float bh = bin[2 * UU + ug];
    const int gbatch = bg * 8 + wp;              // global batch for gate phase

    // ldmatrix lane addressing
    uint32_t a_off  = (uint32_t)(((lane & 15) * H_STRIDE + (lane >> 4) * 8) * 2);
    uint32_t b_addr = smb + OFF_W +
                      (uint32_t)(((lane & 15) * W_STRIDE + 16 * wp + (lane >> 4) * 8) * 2);

    __syncthreads();
    cluster_sync_();   // all CTAs initialized before any remote h writes

    float hn_reg = 0.f;   // fp32 h for this thread's (batch, unit)

    for (int s = 0; s < TT; s++) {
        int t = dir ? (TT - 1 - s) : s;
        int p = s & 1;

        // issue xw loads early (consumed after the mma barrier)
        size_t xrow = ((size_t)gbatch * TT + t) * GG;
        float xz = __ldg(&xw[xrow + ug]);
        float xr = __ldg(&xw[xrow + UU + ug]);
        float xh = __ldg(&xw[xrow + 2 * UU + ug]);

        if (wp < 6) {
            float acc0[4] = {0.f, 0.f, 0.f, 0.f};
            float acc1[4] = {0.f, 0.f, 0.f, 0.f};
            uint32_t abase = smb + OFF_H + (uint32_t)(p * 16 * H_STRIDE * 2) + a_off;
#pragma unroll
            for (int kq = 0; kq < 16; kq++) {
                uint32_t a[4], r0, r1, r2, r3;
                ldsm_x4(a[0], a[1], a[2], a[3], abase + kq * 32);
                ldsm_x4_t(r0, r1, r2, r3, b_addr + kq * 16 * W_STRIDE * 2);
                uint32_t b0[2] = {r0, r1};
                uint32_t b1[2] = {r2, r3};
                mma16816(acc0, a, b0);
                mma16816(acc1, a, b1);
            }
            // store valid rows 0-7 to gate smem
            int row = lane >> 2;
            int c0  = 16 * wp + (lane & 3) * 2;
            *reinterpret_cast<float2*>(&gt[row * GT_STRIDE + c0])     = make_float2(acc0[0], acc0[1]);
            *reinterpret_cast<float2*>(&gt[row * GT_STRIDE + c0 + 8]) = make_float2(acc1[0], acc1[1]);
        }
        __syncthreads();

        // gate phase: warp = batch, lane = unit
        float rz = gt[wp * GT_STRIDE + lane] + bz;
        float rr = gt[wp * GT_STRIDE + 32 + lane] + br;
        float rh = gt[wp * GT_STRIDE + 64 + lane] + bh;
        float z  = 1.f / (1.f + expf(-(xz + rz)));
        float r  = 1.f / (1.f + expf(-(xr + rr)));
        float hh = tanhf(xh + r * rh);
        float hn = z * hn_reg + (1.f - z) * hh;
        hn_reg = hn;

        // broadcast fp16 h to all 8 CTAs' hbuf[p^1]
        float hnb = __shfl_down_sync(0xffffffffu, hn, 1);
        if ((lane & 1) == 0) {
            __half2 pk = __halves2half2(__float2half_rn(hn), __float2half_rn(hnb));
            uint32_t off = smb + OFF_H +
                           (uint32_t)((((p ^ 1) * 16 + wp) * H_STRIDE + ug) * 2);
            uint32_t v = *reinterpret_cast<uint32_t*>(&pk);
#pragma unroll
            for (uint32_t rr2 = 0; rr2 < CLS; rr2++) st_cluster_u32(off, rr2, v);
        }
        if (out_seq)
            out_seq[((size_t)gbatch * TT + t) * (2 * UU) + dir * UU + ug] = __float2half_rn(hn);

        cluster_sync_();
    }

    if (out_final)
        out_final[(size_t)gbatch * (2 * UU) + dir * UU + ug] = hn_reg;
}

// ------------------------------------------------------------------
// 4) Output head
// ------------------------------------------------------------------
__global__ void out_kernel(const float* __restrict__ h2,
                           const float* __restrict__ wout,
                           const float* __restrict__ bout,
                           float* __restrict__ out) {
    int b = blockIdx.x;
    int c = threadIdx.x;
    __shared__ float logits[CC];
    if (c < CC) {
        float acc = bout[c];
        const float* hrow = h2 + (size_t)b * (2 * UU);
#pragma unroll 4
        for (int j = 0; j < 2 * UU; j++) acc += hrow[j] * wout[(size_t)j * CC + c];
        logits[c] = acc;
    }
    __syncthreads();
    if (c == 0) {
        float m = logits[0];
#pragma unroll
        for (int i = 1; i < CC; i++) m = fmaxf(m, logits[i]);
        float s = 0.f;
#pragma unroll
        for (int i = 0; i < CC; i++) { float ev = expf(logits[i] - m); logits[i] = ev; s += ev; }
        float inv = 1.f / s;
#pragma unroll
        for (int i = 0; i < CC; i++) out[(size_t)b * CC + i] = logits[i] * inv;
    }
}

// ------------------------------------------------------------------
// Launcher
// ------------------------------------------------------------------
extern "C" void kernel_launch(void* const* d_in, const int* in_sizes, int n_in,
                              void* d_out, int out_size) {
    const int*   x    = (const int*)  d_in[0];
    const float* emb  = (const float*)d_in[1];
    const float* k1f  = (const float*)d_in[2];
    const float* rk1f = (const float*)d_in[3];
    const float* b1f  = (const float*)d_in[4];
    const float* k1b  = (const float*)d_in[5];
    const float* rk1b = (const float*)d_in[6];
    const float* b1b  = (const float*)d_in[7];
    const float* k2f  = (const float*)d_in[8];
    const float* rk2f = (const float*)d_in[9];
    const float* b2f  = (const float*)d_in[10];
    const float* k2b  = (const float*)d_in[11];
    const float* rk2b = (const float*)d_in[12];
    const float* b2b  = (const float*)d_in[13];
    const float* wout = (const float*)d_in[14];
    const float* bout = (const float*)d_in[15];
    float* out = (float*)d_out;

    __half *eh_p, *h1h_p, *rkhf_p, *rkhb_p, *w1hf_p, *w1hb_p, *w2hf_p, *w2hb_p;
    float *xwf_p, *xwb_p, *h2_p;
    cudaGetSymbolAddress((void**)&eh_p,   g_eh);
    cudaGetSymbolAddress((void**)&h1h_p,  g_h1h);
    cudaGetSymbolAddress((void**)&xwf_p,  g_xwf);
    cudaGetSymbolAddress((void**)&xwb_p,  g_xwb);
    cudaGetSymbolAddress((void**)&h2_p,   g_h2);
    cudaGetSymbolAddress((void**)&rkhf_p, g_rkh_f);
    cudaGetSymbolAddress((void**)&rkhb_p, g_rkh_b);
    cudaGetSymbolAddress((void**)&w1hf_p, g_w1hf);
    cudaGetSymbolAddress((void**)&w1hb_p, g_w1hb);
    cudaGetSymbolAddress((void**)&w2hf_p, g_w2hf);
    cudaGetSymbolAddress((void**)&w2hb_p, g_w2hb);

    cudaFuncSetAttribute(gru_cluster,
                         cudaFuncAttributeMaxDynamicSharedMemorySize, GRU_SMEM2);

    const int M = BB * TT;               // 32768
    dim3 hgrid(GG / 128, M / 128);       // (6, 256)
    const int RKN = UU * GG;

    // 0) weight conversions
    f2h_pad_kernel<<<(KE * GG + 1023) / 1024, 1024>>>(k1f, w1hf_p, EE, KE, GG);
    f2h_pad_kernel<<<(KE * GG + 1023) / 1024, 1024>>>(k1b, w1hb_p, EE, KE, GG);
    f2h_kernel<<<(2 * UU * GG + 1023) / 1024, 1024>>>(k2f, w2hf_p, 2 * UU * GG);
    f2h_kernel<<<(2 * UU * GG + 1023) / 1024, 1024>>>(k2b, w2hb_p, 2 * UU * GG);
    f2h_kernel<<<(RKN + 1023) / 1024, 1024>>>(rk1f, rkhf_p, RKN);
    f2h_kernel<<<(RKN + 1023) / 1024, 1024>>>(rk1b, rkhb_p, RKN);

    // 1) embedding gather -> fp16 padded
    gather_h_kernel<<<M, 160>>>(x, emb, eh_p);

    // 2) layer-1 input projections (tensor cores)
    hgemm_bias<<<hgrid, 256>>>(eh_p, w1hf_p, b1f, xwf_p, KE, KE);
    hgemm_bias<<<hgrid, 256>>>(eh_p, w1hb_p, b1b, xwb_p, KE, KE);

    // 3) layer-1 recurrence (clustered, tensor-core)
    gru_cluster<<<128, 256, GRU_SMEM2>>>(xwf_p, xwb_p, rkhf_p, rkhb_p,
                                         b1f + GG, b1b + GG, h1h_p, nullptr);

    // 3b) layer-2 recurrent weight conversion (buffer reuse; stream-ordered)
    f2h_kernel<<<(RKN + 1023) / 1024, 1024>>>(rk2f, rkhf_p, RKN);
    f2h_kernel<<<(RKN + 1023) / 1024, 1024>>>(rk2b, rkhb_p, RKN);

    // 4) layer-2 input projections
    hgemm_bias<<<hgrid, 256>>>(h1h_p, w2hf_p, b2f, xwf_p, 2 * UU, 2 * UU);
    hgemm_bias<<<hgrid, 256>>>(h1h_p, w2hb_p, b2b, xwb_p, 2 * UU, 2 * UU);

    // 5) layer-2 recurrence, final states only
    gru_cluster<<<128, 256, GRU_SMEM2>>>(xwf_p, xwb_p, rkhf_p, rkhb_p,
                                         b2f + GG, b2b + GG, nullptr, h2_p);

    // 6) output head + softmax
    out_kernel<<<BB, 32>>>(h2_p, wout, bout, out);
}

// round 6
// speedup vs baseline: 17.7875x; 1.3531x over previous
#include <cuda_runtime.h>
#include <cuda_fp16.h>
#include <math.h>
#include <stdint.h>

// Problem dims
#define BB 64
#define TT 512
#define EE 300
#define KE 320          // padded embedding K (multiple of 32)
#define UU 256
#define GG 768
#define CC 20

// ------------------------------------------------------------------
// Scratch (device globals; allocation inside kernel_launch is banned)
// ------------------------------------------------------------------
__device__ __half g_eh  [BB * TT * KE];      // fp16 embedded input [B*T, 320]
__device__ __half g_h1h [BB * TT * 2 * UU];  // fp16 layer-1 output [B*T, 512]
__device__ float  g_xwf [BB * TT * GG];      // xw forward  [B*T, 768] fp32
__device__ float  g_xwb [BB * TT * GG];      // xw backward [B*T, 768] fp32
__device__ float  g_h2  [BB * 2 * UU];       // layer-2 final [B, 512]
__device__ __half g_rkh1f[UU * GG];          // fp16 recurrent weights L1 fwd
__device__ __half g_rkh1b[UU * GG];          // fp16 recurrent weights L1 bwd
__device__ __half g_rkh2f[UU * GG];          // fp16 recurrent weights L2 fwd
__device__ __half g_rkh2b[UU * GG];          // fp16 recurrent weights L2 bwd
__device__ __half g_w1hf[KE * GG];           // fp16 padded k1f
__device__ __half g_w1hb[KE * GG];           // fp16 padded k1b
__device__ __half g_w2hf[2 * UU * GG];       // fp16 k2f
__device__ __half g_w2hb[2 * UU * GG];       // fp16 k2b

// ------------------------------------------------------------------
// 0) All fp32 -> fp16 weight conversions in ONE kernel (8 segments)
// ------------------------------------------------------------------
__global__ void convert_all(const float* __restrict__ rk1f, const float* __restrict__ rk1b,
                            const float* __restrict__ rk2f, const float* __restrict__ rk2b,
                            const float* __restrict__ k1f,  const float* __restrict__ k1b,
                            const float* __restrict__ k2f,  const float* __restrict__ k2b,
                            __half* rkh1f, __half* rkh1b, __half* rkh2f, __half* rkh2b,
                            __half* w1hf,  __half* w1hb,  __half* w2hf,  __half* w2hb) {
    int seg = blockIdx.y;
    int i = blockIdx.x * blockDim.x + threadIdx.x;
    const float* src = nullptr; __half* dst = nullptr; int n = 0; bool pad = false;
    switch (seg) {
        case 0: src = rk1f; dst = rkh1f; n = UU * GG; break;
        case 1: src = rk1b; dst = rkh1b; n = UU * GG; break;
        case 2: src = rk2f; dst = rkh2f; n = UU * GG; break;
        case 3: src = rk2b; dst = rkh2b; n = UU * GG; break;
        case 4: src = k1f;  dst = w1hf;  n = KE * GG; pad = true; break;
        case 5: src = k1b;  dst = w1hb;  n = KE * GG; pad = true; break;
        case 6: src = k2f;  dst = w2hf;  n = 2 * UU * GG; break;
        default: src = k2b; dst = w2hb;  n = 2 * UU * GG; break;
    }
    if (i >= n) return;
    if (pad) {
        int r = i / GG;
        dst[i] = (r < EE) ? __float2half_rn(src[i]) : __half(0.f);
    } else {
        dst[i] = __float2half_rn(src[i]);
    }
}

// ------------------------------------------------------------------
// 1) Embedding gather straight to fp16, K padded to 320
// ------------------------------------------------------------------
__global__ void gather_h_kernel(const int* __restrict__ x,
                                const float* __restrict__ emb,
                                __half* __restrict__ eh) {
    int row = blockIdx.x;
    int t = threadIdx.x;
    const float* src = emb + (size_t)x[row] * EE;
    __half2* dst = reinterpret_cast<__half2*>(eh + (size_t)row * KE);
    if (t < EE / 2) {
        float2 v = *reinterpret_cast<const float2*>(src + 2 * t);
        dst[t] = __floats2half2_rn(v.x, v.y);
    } else if (t < KE / 2) {
        dst[t] = __floats2half2_rn(0.f, 0.f);
    }
}

// ------------------------------------------------------------------
// mma/ldmatrix primitives
// ------------------------------------------------------------------
__device__ __forceinline__ void ldsm_x4(uint32_t& r0, uint32_t& r1, uint32_t& r2, uint32_t& r3,
                                        uint32_t addr) {
    asm volatile("ldmatrix.sync.aligned.m8n8.x4.shared.b16 {%0,%1,%2,%3}, [%4];"
                 : "=r"(r0), "=r"(r1), "=r"(r2), "=r"(r3) : "r"(addr));
}
__device__ __forceinline__ void ldsm_x4_t(uint32_t& r0, uint32_t& r1, uint32_t& r2, uint32_t& r3,
                                          uint32_t addr) {
    asm volatile("ldmatrix.sync.aligned.m8n8.x4.trans.shared.b16 {%0,%1,%2,%3}, [%4];"
                 : "=r"(r0), "=r"(r1), "=r"(r2), "=r"(r3) : "r"(addr));
}
__device__ __forceinline__ void ldsm_x2(uint32_t& r0, uint32_t& r1, uint32_t addr) {
    asm volatile("ldmatrix.sync.aligned.m8n8.x2.shared.b16 {%0,%1}, [%2];"
                 : "=r"(r0), "=r"(r1) : "r"(addr));
}
__device__ __forceinline__ void mma16816(float* c, const uint32_t* a, const uint32_t* b) {
    asm volatile("mma.sync.aligned.m16n8k16.row.col.f32.f16.f16.f32 "
                 "{%0,%1,%2,%3}, {%4,%5,%6,%7}, {%8,%9}, {%0,%1,%2,%3};"
                 : "+f"(c[0]), "+f"(c[1]), "+f"(c[2]), "+f"(c[3])
                 : "r"(a[0]), "r"(a[1]), "r"(a[2]), "r"(a[3]), "r"(b[0]), "r"(b[1]));
}

#define CPA16(s, g) asm volatile("cp.async.cg.shared.global [%0], [%1], 16;" :: "r"(s), "l"(g))
#define CPA_COMMIT() asm volatile("cp.async.commit_group;" ::: "memory")
#define CPA_WAIT1()  asm volatile("cp.async.wait_group 1;" ::: "memory")

// ------------------------------------------------------------------
// 2) HGEMM with bias, cp.async double-buffered
// ------------------------------------------------------------------
#define SA 56
#define SB 136

__global__ __launch_bounds__(256)
void hgemm_bias(const __half* __restrict__ A, const __half* __restrict__ Bw,
                const float* __restrict__ bias, float* __restrict__ C,
                int K, int lda) {
    __shared__ __half As[2][128 * SA];
    __shared__ __half Bs[2][32 * SB];
    const uint32_t AS_BYTES = 128 * SA * 2;
    const uint32_t BS_BYTES = 32 * SB * 2;

    int tid  = threadIdx.x;
    int w    = tid >> 5;
    int lane = tid & 31;
    int bm   = blockIdx.y * 128;
    int bn   = blockIdx.x * 128;
    int wm   = (w >> 2) * 64;
    int wn   = (w & 3) * 32;

    float acc[4][4][4];
#pragma unroll
    for (int mi = 0; mi < 4; mi++)
#pragma unroll
        for (int ni = 0; ni < 4; ni++)
#pragma unroll
            for (int c = 0; c < 4; c++) acc[mi][ni][c] = 0.f;

    int arow = tid >> 1, acol = (tid & 1) * 16;
    int brow = tid >> 3, bcol = (tid & 7) * 16;
    const __half* Ag = A + (size_t)(bm + arow) * lda + acol;
    const __half* Bg = Bw + (size_t)brow * GG + bn + bcol;

    uint32_t as_st = (uint32_t)__cvta_generic_to_shared(&As[0][arow * SA + acol]);
    uint32_t bs_st = (uint32_t)__cvta_generic_to_shared(&Bs[0][brow * SB + bcol]);

    uint32_t a_addr[4], b_addr[2];
#pragma unroll
    for (int mi = 0; mi < 4; mi++) {
        int m  = wm + mi * 16 + (lane & 15);
        int kc = (lane >> 4) * 8;
        a_addr[mi] = (uint32_t)__cvta_generic_to_shared(&As[0][m * SA + kc]);
    }
#pragma unroll
    for (int nj = 0; nj < 2; nj++) {
        int kr = lane & 15;
        int nc = wn + nj * 16 + (lane >> 4) * 8;
        b_addr[nj] = (uint32_t)__cvta_generic_to_shared(&Bs[0][kr * SB + nc]);
    }

    int KT = K >> 5;

    // prologue: issue tile 0 into buffer 0
    {
        CPA16(as_st, Ag);
        CPA16(as_st + 16, Ag + 8);
        CPA16(bs_st, Bg);
        CPA16(bs_st + 16, Bg + 8);
        CPA_COMMIT();
    }

    for (int kt = 0; kt < KT; kt++) {
        int cur = kt & 1;
        if (kt + 1 < KT) {
            int nb = cur ^ 1;
            const __half* Agn = Ag + (kt + 1) * 32;
            const __half* Bgn = Bg + (size_t)(kt + 1) * 32 * GG;
            CPA16(as_st + nb * AS_BYTES, Agn);
            CPA16(as_st + nb * AS_BYTES + 16, Agn + 8);
            CPA16(bs_st + nb * BS_BYTES, Bgn);
            CPA16(bs_st + nb * BS_BYTES + 16, Bgn + 8);
        }
        CPA_COMMIT();            // (possibly empty) group keeps the count consistent
        CPA_WAIT1();             // tile kt landed
        __syncthreads();

        uint32_t aoff = cur * AS_BYTES;
        uint32_t boff = cur * BS_BYTES;
#pragma unroll
        for (int kk = 0; kk < 2; kk++) {
            uint32_t afr[4][4];
            uint32_t bfr[4][2];
#pragma unroll
            for (int mi = 0; mi < 4; mi++)
                ldsm_x4(afr[mi][0], afr[mi][1], afr[mi][2], afr[mi][3],
                        a_addr[mi] + aoff + kk * 16 * 2);
#pragma unroll
            for (int nj = 0; nj < 2; nj++) {
                uint32_t r0, r1, r2, r3;
                ldsm_x4_t(r0, r1, r2, r3, b_addr[nj] + boff + kk * 16 * SB * 2);
                bfr[2 * nj][0] = r0; bfr[2 * nj][1] = r1;
                bfr[2 * nj + 1][0] = r2; bfr[2 * nj + 1][1] = r3;
            }
#pragma unroll
            for (int mi = 0; mi < 4; mi++)
#pragma unroll
                for (int ni = 0; ni < 4; ni++)
                    mma16816(acc[mi][ni], afr[mi], bfr[ni]);
        }
        __syncthreads();
    }

#pragma unroll
    for (int mi = 0; mi < 4; mi++) {
#pragma unroll
        for (int ni = 0; ni < 4; ni++) {
            int r0 = bm + wm + mi * 16 + (lane >> 2);
            int c0 = bn + wn + ni * 8 + (lane & 3) * 2;
            float bv0 = bias[c0], bv1 = bias[c0 + 1];
            float* p0 = C + (size_t)r0 * GG + c0;
            float* p1 = C + (size_t)(r0 + 8) * GG + c0;
            p0[0] = acc[mi][ni][0] + bv0;
            p0[1] = acc[mi][ni][1] + bv1;
            p1[0] = acc[mi][ni][2] + bv0;
            p1[1] = acc[mi][ni][3] + bv1;
        }
    }
}

// ------------------------------------------------------------------
// 3) GRU recurrence: cluster(8), SMEM weights -> B-frags hoisted to regs,
//    A via ldmatrix.x2 (8 real batch rows), fast gates, xw prefetch,
//    split cluster arrive/wait.
// ------------------------------------------------------------------
#define CLS 8
#define W_STRIDE 104
#define H_STRIDE 264
#define GT_STRIDE 100
#define OFF_W 0
#define OFF_H (256 * W_STRIDE * 2)
#define OFF_G (OFF_H + 2 * 16 * H_STRIDE * 2)
#define GRU_SMEM2 (OFF_G + 8 * GT_STRIDE * 4)

__device__ __forceinline__ void st_cluster_u32(uint32_t laddr, uint32_t rnk, uint32_t v) {
    uint32_t ra;
    asm volatile("mapa.shared::cluster.u32 %0, %1, %2;" : "=r"(ra) : "r"(laddr), "r"(rnk));
    asm volatile("st.shared::cluster.u32 [%0], %1;" :: "r"(ra), "r"(v));
}
__device__ __forceinline__ void cluster_arrive_() {
    asm volatile("barrier.cluster.arrive.aligned;" ::: "memory");
}
__device__ __forceinline__ void cluster_wait_() {
    asm volatile("barrier.cluster.wait.aligned;" ::: "memory");
}
__device__ __forceinline__ float fsig(float x) {
    return __fdividef(1.f, 1.f + __expf(-x));
}
__device__ __forceinline__ float ftanh(float x) {
    return __fdividef(2.f, 1.f + __expf(-2.f * x)) - 1.f;
}

__global__ __launch_bounds__(256) __cluster_dims__(CLS, 1, 1)
void gru_cluster(const float* __restrict__ xw_f, const float* __restrict__ xw_b,
                 const __half* __restrict__ rkh_f, const __half* __restrict__ rkh_b,
                 const float* __restrict__ bin_f, const float* __restrict__ bin_b,
                 __half* __restrict__ out_seq,   // [B*T, 512] fp16 or nullptr
                 float* __restrict__ out_final)  // [B, 512] or nullptr
{
    extern __shared__ char sm[];
    __half* wsm  = reinterpret_cast<__half*>(sm + OFF_W);   // [256][W_STRIDE]
    __half* hbuf = reinterpret_cast<__half*>(sm + OFF_H);   // [2][16][H_STRIDE]
    float*  gt   = reinterpret_cast<float*>(sm + OFF_G);    // [8][GT_STRIDE]
    uint32_t smb = (uint32_t)__cvta_generic_to_shared(sm);

    int tid = threadIdx.x;
    int lane = tid & 31;
    int wp = tid >> 5;
    uint32_t rank;
    asm("mov.u32 %0, %%cluster_ctarank;" : "=r"(rank));
    int cl  = blockIdx.x / CLS;
    int dir = cl >> 3;
    int bg  = cl & 7;

    const float*  xw  = dir ? xw_b  : xw_f;
    const __half* rkh = dir ? rkh_b : rkh_f;
    const float*  bin = dir ? bin_b : bin_f;

    // one-time: load this CTA's 96 weight cols, zero h buffers
    for (int i = tid; i < 256 * 96; i += 256) {
        int k = i / 96, j = i % 96;
        int gcol = (j >> 5) * 256 + (rank << 5) + (j & 31);
        wsm[k * W_STRIDE + j] = rkh[(size_t)k * GG + gcol];
    }
    for (int i = tid; i < 2 * 16 * H_STRIDE; i += 256) hbuf[i] = __half(0.f);

    const int ug = (rank << 5) + lane;
    const float bz = bin[ug];
    const float br = bin[UU + ug];
    const float bh = bin[2 * UU + ug];
    const int gbatch = bg * 8 + wp;

    // A (h) ldmatrix.x2 lane addressing: lanes 0-7 -> rows 0-7 k+0,
    // lanes 8-15 -> rows 0-7 k+8 (rows 8-15 of the m16 tile are zeros).
    uint32_t a_off = (uint32_t)((((lane & 7) * H_STRIDE) + ((lane >> 3) & 1) * 8) * 2);
    uint32_t b_addr = smb + OFF_W +
                      (uint32_t)(((lane & 15) * W_STRIDE + 16 * wp + (lane >> 4) * 8) * 2);

    __syncthreads();

    // Hoist B (weight) fragments into registers: loop-invariant across steps.
    uint32_t bReg[16][4];
    if (wp < 6) {
#pragma unroll
        for (int kq = 0; kq < 16; kq++)
            ldsm_x4_t(bReg[kq][0], bReg[kq][1], bReg[kq][2], bReg[kq][3],
                      b_addr + kq * 16 * W_STRIDE * 2);
    }

    cluster_arrive_();
    cluster_wait_();   // all CTAs initialized before any remote h writes

    float hn_reg = 0.f;

    // preload xw for step 0
    float xz, xr, xh;
    {
        int t0 = dir ? (TT - 1) : 0;
        size_t xrow = ((size_t)gbatch * TT + t0) * GG;
        xz = __ldg(&xw[xrow + ug]);
        xr = __ldg(&xw[xrow + UU + ug]);
        xh = __ldg(&xw[xrow + 2 * UU + ug]);
    }

    for (int s = 0; s < TT; s++) {
        int t = dir ? (TT - 1 - s) : s;
        int p = s & 1;

        if (wp < 6) {
            float acc0[4] = {0.f, 0.f, 0.f, 0.f};
            float acc1[4] = {0.f, 0.f, 0.f, 0.f};
            uint32_t abase = smb + OFF_H + (uint32_t)(p * 16 * H_STRIDE * 2) + a_off;
#pragma unroll
            for (int kq = 0; kq < 16; kq++) {
                uint32_t a[4];
                a[1] = 0u; a[3] = 0u;
                ldsm_x2(a[0], a[2], abase + kq * 32);
                mma16816(acc0, a, &bReg[kq][0]);
                mma16816(acc1, a, &bReg[kq][2]);
            }
            int row = lane >> 2;
            int c0  = 16 * wp + (lane & 3) * 2;
            *reinterpret_cast<float2*>(&gt[row * GT_STRIDE + c0])     = make_float2(acc0[0], acc0[1]);
            *reinterpret_cast<float2*>(&gt[row * GT_STRIDE + c0 + 8]) = make_float2(acc1[0], acc1[1]);
        }

        // prefetch xw for step s+1 (hidden under mma + barrier)
        float xzn = 0.f, xrn = 0.f, xhn = 0.f;
        if (s + 1 < TT) {
            int tn = dir ? (TT - 2 - s) : (s + 1);
            size_t xrow = ((size_t)gbatch * TT + tn) * GG;
            xzn = __ldg(&xw[xrow + ug]);
            xrn = __ldg(&xw[xrow + UU + ug]);
            xhn = __ldg(&xw[xrow + 2 * UU + ug]);
        }
        __syncthreads();

        // gate phase: warp = batch, lane = unit
        float rz = gt[wp * GT_STRIDE + lane] + bz;
        float rr = gt[wp * GT_STRIDE + 32 + lane] + br;
        float rh = gt[wp * GT_STRIDE + 64 + lane] + bh;
        float z  = fsig(xz + rz);
        float r  = fsig(xr + rr);
        float hh = ftanh(xh + r * rh);
        float hn = z * hn_reg + (1.f - z) * hh;
        hn_reg = hn;

        // broadcast fp16 h to all 8 CTAs' hbuf[p^1]
        float hnb = __shfl_down_sync(0xffffffffu, hn, 1);
        if ((lane & 1) == 0) {
            __half2 pk = __halves2half2(__float2half_rn(hn), __float2half_rn(hnb));
            uint32_t off = smb + OFF_H +
                           (uint32_t)((((p ^ 1) * 16 + wp) * H_STRIDE + ug) * 2);
            uint32_t v = *reinterpret_cast<uint32_t*>(&pk);
#pragma unroll
            for (uint32_t rr2 = 0; rr2 < CLS; rr2++) st_cluster_u32(off, rr2, v);
        }
        cluster_arrive_();

        if (out_seq)
            out_seq[((size_t)gbatch * TT + t) * (2 * UU) + dir * UU + ug] = __float2half_rn(hn);
        xz = xzn; xr = xrn; xh = xhn;

        cluster_wait_();
    }

    if (out_final)
        out_final[(size_t)gbatch * (2 * UU) + dir * UU + ug] = hn_reg;
}

// ------------------------------------------------------------------
// 4) Output head
// ------------------------------------------------------------------
__global__ void out_kernel(const float* __restrict__ h2,
                           const float* __restrict__ wout,
                           const float* __restrict__ bout,
                           float* __restrict__ out) {
    int b = blockIdx.x;
    int c = threadIdx.x;
    __shared__ float logits[CC];
    if (c < CC) {
        float acc = bout[c];
        const float* hrow = h2 + (size_t)b * (2 * UU);
#pragma unroll 4
        for (int j = 0; j < 2 * UU; j++) acc += hrow[j] * wout[(size_t)j * CC + c];
        logits[c] = acc;
    }
    __syncthreads();
    if (c == 0) {
        float m = logits[0];
#pragma unroll
        for (int i = 1; i < CC; i++) m = fmaxf(m, logits[i]);
        float s = 0.f;
#pragma unroll
        for (int i = 0; i < CC; i++) { float ev = expf(logits[i] - m); logits[i] = ev; s += ev; }
        float inv = 1.f / s;
#pragma unroll
        for (int i = 0; i < CC; i++) out[(size_t)b * CC + i] = logits[i] * inv;
    }
}

// ------------------------------------------------------------------
// Launcher
// ------------------------------------------------------------------
extern "C" void kernel_launch(void* const* d_in, const int* in_sizes, int n_in,
                              void* d_out, int out_size) {
    const int*   x    = (const int*)  d_in[0];
    const float* emb  = (const float*)d_in[1];
    const float* k1f  = (const float*)d_in[2];
    const float* rk1f = (const float*)d_in[3];
    const float* b1f  = (const float*)d_in[4];
    const float* k1b  = (const float*)d_in[5];
    const float* rk1b = (const float*)d_in[6];
    const float* b1b  = (const float*)d_in[7];
    const float* k2f  = (const float*)d_in[8];
    const float* rk2f = (const float*)d_in[9];
    const float* b2f  = (const float*)d_in[10];
    const float* k2b  = (const float*)d_in[11];
    const float* rk2b = (const float*)d_in[12];
    const float* b2b  = (const float*)d_in[13];
    const float* wout = (const float*)d_in[14];
    const float* bout = (const float*)d_in[15];
    float* out = (float*)d_out;

    __half *eh_p, *h1h_p, *rkh1f_p, *rkh1b_p, *rkh2f_p, *rkh2b_p;
    __half *w1hf_p, *w1hb_p, *w2hf_p, *w2hb_p;
    float *xwf_p, *xwb_p, *h2_p;
    cudaGetSymbolAddress((void**)&eh_p,    g_eh);
    cudaGetSymbolAddress((void**)&h1h_p,   g_h1h);
    cudaGetSymbolAddress((void**)&xwf_p,   g_xwf);
    cudaGetSymbolAddress((void**)&xwb_p,   g_xwb);
    cudaGetSymbolAddress((void**)&h2_p,    g_h2);
    cudaGetSymbolAddress((void**)&rkh1f_p, g_rkh1f);
    cudaGetSymbolAddress((void**)&rkh1b_p, g_rkh1b);
    cudaGetSymbolAddress((void**)&rkh2f_p, g_rkh2f);
    cudaGetSymbolAddress((void**)&rkh2b_p, g_rkh2b);
    cudaGetSymbolAddress((void**)&w1hf_p,  g_w1hf);
    cudaGetSymbolAddress((void**)&w1hb_p,  g_w1hb);
    cudaGetSymbolAddress((void**)&w2hf_p,  g_w2hf);
    cudaGetSymbolAddress((void**)&w2hb_p,  g_w2hb);

    cudaFuncSetAttribute(gru_cluster,
                         cudaFuncAttributeMaxDynamicSharedMemorySize, GRU_SMEM2);

    const int M = BB * TT;               // 32768
    dim3 hgrid(GG / 128, M / 128);       // (6, 256)

    // 0) all weight conversions, one kernel
    convert_all<<<dim3(384, 8), 1024>>>(rk1f, rk1b, rk2f, rk2b, k1f, k1b, k2f, k2b,
                                        rkh1f_p, rkh1b_p, rkh2f_p, rkh2b_p,
                                        w1hf_p, w1hb_p, w2hf_p, w2hb_p);

    // 1) embedding gather -> fp16 padded
    gather_h_kernel<<<M, 160>>>(x, emb, eh_p);

    // 2) layer-1 input projections (tensor cores, pipelined)
    hgemm_bias<<<hgrid, 256>>>(eh_p, w1hf_p, b1f, xwf_p, KE, KE);
    hgemm_bias<<<hgrid, 256>>>(eh_p, w1hb_p, b1b, xwb_p, KE, KE);

    // 3) layer-1 recurrence (clustered, tensor-core)
    gru_cluster<<<128, 256, GRU_SMEM2>>>(xwf_p, xwb_p, rkh1f_p, rkh1b_p,
                                         b1f + GG, b1b + GG, h1h_p, nullptr);

    // 4) layer-2 input projections
    hgemm_bias<<<hgrid, 256>>>(h1h_p, w2hf_p, b2f, xwf_p, 2 * UU, 2 * UU);
    hgemm_bias<<<hgrid, 256>>>(h1h_p, w2hb_p, b2b, xwb_p, 2 * UU, 2 * UU);

    // 5) layer-2 recurrence, final states only
    gru_cluster<<<128, 256, GRU_SMEM2>>>(xwf_p, xwb_p, rkh2f_p, rkh2b_p,
                                         b2f + GG, b2b + GG, nullptr, h2_p);

    // 6) output head + softmax
    out_kernel<<<BB, 32>>>(h2_p, wout, bout, out);
}